// round 3
// baseline (speedup 1.0000x reference)
#include <cuda_runtime.h>
#include <math.h>

// Problem dims
#define MROWS 16384   // B*N
#define DDIM  1024
#define NSEQ  2048
#define NBATCH 8

// ---------------- scratch (device globals; no allocations allowed) --------
__device__ float g_V [MROWS * DDIM];            // sigmoid(bn(x@Wv))       64MB
__device__ float g_VW[MROWS * DDIM];            // V @ Wo                  64MB
__device__ float g_P1[NBATCH * (NSEQ + 1) * DDIM]; // prefix e^{+2tK}*VW   67MB
__device__ float g_P2[NBATCH * (NSEQ + 1) * DDIM]; // prefix e^{-2tK}*VW   67MB
__device__ float g_qpart[MROWS * 8];
__device__ float g_kpart[MROWS * 8];
__device__ float g_tQ[MROWS];
__device__ float g_tK[MROWS];
__device__ float g_tKs[NBATCH * NSEQ];          // sorted tK per batch
__device__ float g_E1 [NBATCH * NSEQ];          // e^{+2 tKs}
__device__ float g_E2 [NBATCH * NSEQ];          // e^{-2 tKs}
__device__ int   g_perm[NBATCH * NSEQ];         // sort permutation
__device__ float g_vsum[NBATCH * DDIM];         // unweighted colsum of VW

// ---------------- packed f32x2 helpers ------------------------------------
__device__ __forceinline__ unsigned long long pk2(float x, float y) {
    unsigned long long r;
    asm("mov.b64 %0, {%1, %2};" : "=l"(r) : "f"(x), "f"(y));
    return r;
}
__device__ __forceinline__ void upk2(unsigned long long v, float& x, float& y) {
    asm("mov.b64 {%0, %1}, %2;" : "=f"(x), "=f"(y) : "l"(v));
}
__device__ __forceinline__ void fma2(unsigned long long& c,
                                     unsigned long long a, unsigned long long b) {
    asm("fma.rn.f32x2 %0, %1, %2, %0;" : "+l"(c) : "l"(a), "l"(b));
}

// ---------------- GEMM: 128x128 tile, K-step 16, 8x8 per thread -----------
// MODE 0: bn+sigmoid epilogue, per-row partial sums -> g_qpart/g_kpart
// MODE 1: bn+sigmoid epilogue, write g_V
// MODE 2: plain GEMM of g_V @ Bm -> g_VW
template <int MODE>
__global__ void __launch_bounds__(256)
gemm_kernel(const float* __restrict__ A, const float* __restrict__ Bm,
            const float* __restrict__ mean, const float* __restrict__ gam,
            const float* __restrict__ var, const float* __restrict__ beta,
            int which)
{
    __shared__ float As[16][128];
    __shared__ float Bs[16][128];
    __shared__ float red[128][17];

    const int tid = threadIdx.x;
    const int bc = blockIdx.x;   // 0..7   (col tile)
    const int br = blockIdx.y;   // 0..127 (row tile)
    const int tx = tid & 15, ty = tid >> 4;
    const float* Ap = (MODE == 2) ? g_V : A;

    unsigned long long c[8][4];
#pragma unroll
    for (int i = 0; i < 8; i++)
#pragma unroll
        for (int j = 0; j < 4; j++) c[i][j] = 0ull;

    for (int kb = 0; kb < DDIM; kb += 16) {
#pragma unroll
        for (int l = 0; l < 2; l++) {
            int idx = tid + l * 256;              // 0..511 float4 slots
            int arow = idx >> 2, akq = (idx & 3) << 2;
            float4 va = *(const float4*)(Ap + (size_t)(br * 128 + arow) * DDIM + kb + akq);
            As[akq + 0][arow] = va.x; As[akq + 1][arow] = va.y;
            As[akq + 2][arow] = va.z; As[akq + 3][arow] = va.w;
            int krow = idx >> 5, nq = idx & 31;
            *(float4*)&Bs[krow][nq << 2] =
                *(const float4*)(Bm + (size_t)(kb + krow) * DDIM + bc * 128 + (nq << 2));
        }
        __syncthreads();
#pragma unroll
        for (int kk = 0; kk < 16; kk++) {
            float4 a0 = *(const float4*)&As[kk][ty * 8];
            float4 a1 = *(const float4*)&As[kk][ty * 8 + 4];
            float4 b0 = *(const float4*)&Bs[kk][tx * 8];
            float4 b1 = *(const float4*)&Bs[kk][tx * 8 + 4];
            unsigned long long bb0 = pk2(b0.x, b0.y), bb1 = pk2(b0.z, b0.w);
            unsigned long long bb2 = pk2(b1.x, b1.y), bb3 = pk2(b1.z, b1.w);
            float av[8] = {a0.x, a0.y, a0.z, a0.w, a1.x, a1.y, a1.z, a1.w};
#pragma unroll
            for (int i = 0; i < 8; i++) {
                unsigned long long aa = pk2(av[i], av[i]);
                fma2(c[i][0], aa, bb0); fma2(c[i][1], aa, bb1);
                fma2(c[i][2], aa, bb2); fma2(c[i][3], aa, bb3);
            }
        }
        __syncthreads();
    }

    const int col0 = bc * 128 + tx * 8;
    const int row0 = br * 128 + ty * 8;

    if (MODE == 2) {
#pragma unroll
        for (int i = 0; i < 8; i++) {
            float v0, v1, v2, v3, v4, v5, v6, v7;
            upk2(c[i][0], v0, v1); upk2(c[i][1], v2, v3);
            upk2(c[i][2], v4, v5); upk2(c[i][3], v6, v7);
            float4 o0 = make_float4(v0, v1, v2, v3);
            float4 o1 = make_float4(v4, v5, v6, v7);
            *(float4*)(g_VW + (size_t)(row0 + i) * DDIM + col0)     = o0;
            *(float4*)(g_VW + (size_t)(row0 + i) * DDIM + col0 + 4) = o1;
        }
    } else {
        float mm[8], sc[8], bt[8];
#pragma unroll
        for (int j = 0; j < 8; j++) {
            mm[j] = mean[col0 + j];
            sc[j] = gam[col0 + j] * rsqrtf(var[col0 + j] + 1e-5f);
            bt[j] = beta[col0 + j];
        }
#pragma unroll
        for (int i = 0; i < 8; i++) {
            float raw[8];
            upk2(c[i][0], raw[0], raw[1]); upk2(c[i][1], raw[2], raw[3]);
            upk2(c[i][2], raw[4], raw[5]); upk2(c[i][3], raw[6], raw[7]);
            float val[8];
#pragma unroll
            for (int j = 0; j < 8; j++) {
                float h = (raw[j] - mm[j]) * sc[j] + bt[j];
                // sigmoid(4*(h-1)) = 1/(1+exp(4-4h))
                val[j] = 1.0f / (1.0f + __expf(4.0f - 4.0f * h));
            }
            if (MODE == 1) {
                float4 o0 = make_float4(val[0], val[1], val[2], val[3]);
                float4 o1 = make_float4(val[4], val[5], val[6], val[7]);
                *(float4*)(g_V + (size_t)(row0 + i) * DDIM + col0)     = o0;
                *(float4*)(g_V + (size_t)(row0 + i) * DDIM + col0 + 4) = o1;
            } else {
                float s = 0.0f;
#pragma unroll
                for (int j = 0; j < 8; j++) s += val[j];
                red[ty * 8 + i][tx] = s;
            }
        }
        if (MODE == 0) {
            __syncthreads();
            if (tid < 128) {
                float s = 0.0f;
#pragma unroll
                for (int j = 0; j < 16; j++) s += red[tid][j];
                float* part = which ? g_kpart : g_qpart;
                part[(size_t)(br * 128 + tid) * 8 + bc] = s;   // deterministic
            }
        }
    }
}

// ---------------- t = 1 - mean --------------------------------------------
__global__ void reduce_t_kernel() {
    int i = blockIdx.x * blockDim.x + threadIdx.x;
    if (i < MROWS) {
        float sq = 0.0f, sk = 0.0f;
#pragma unroll
        for (int j = 0; j < 8; j++) { sq += g_qpart[i * 8 + j]; sk += g_kpart[i * 8 + j]; }
        g_tQ[i] = 1.0f - sq * (1.0f / 1024.0f);
        g_tK[i] = 1.0f - sk * (1.0f / 1024.0f);
    }
}

// ---------------- bitonic sort of tK per batch (2048 elems) ---------------
__global__ void __launch_bounds__(1024) sort_kernel() {
    __shared__ float sv[NSEQ];
    __shared__ int   si[NSEQ];
    const int b = blockIdx.x, t = threadIdx.x;
    sv[t]        = g_tK[b * NSEQ + t];        si[t]        = t;
    sv[t + 1024] = g_tK[b * NSEQ + t + 1024]; si[t + 1024] = t + 1024;
    __syncthreads();
    for (int k = 2; k <= NSEQ; k <<= 1) {
        for (int j = k >> 1; j > 0; j >>= 1) {
#pragma unroll
            for (int l = 0; l < 2; l++) {
                int idx = t + l * 1024;
                int ixj = idx ^ j;
                if (ixj > idx) {
                    bool asc = ((idx & k) == 0);
                    float a = sv[idx], bvv = sv[ixj];
                    if ((a > bvv) == asc) {
                        sv[idx] = bvv; sv[ixj] = a;
                        int tmp = si[idx]; si[idx] = si[ixj]; si[ixj] = tmp;
                    }
                }
            }
            __syncthreads();
        }
    }
#pragma unroll
    for (int l = 0; l < 2; l++) {
        int idx = t + l * 1024;
        float tk = sv[idx];
        g_tKs [b * NSEQ + idx] = tk;
        g_perm[b * NSEQ + idx] = si[idx];
        g_E1  [b * NSEQ + idx] = expf( 2.0f * tk);
        g_E2  [b * NSEQ + idx] = expf(-2.0f * tk);
    }
}

// ---------------- weighted prefix sums over VW rows in sorted order -------
// grid (16, 8), 64 threads: block covers batch=by, d-range [bx*64, bx*64+64)
__global__ void __launch_bounds__(64) scan_kernel() {
    const int b  = blockIdx.y;
    const int d  = blockIdx.x * 64 + threadIdx.x;
    const float* vwb = g_VW + (size_t)b * NSEQ * DDIM;
    float a0 = 0.0f, a1 = 0.0f, a2 = 0.0f;
    g_P1[(size_t)(b * (NSEQ + 1)) * DDIM + d] = 0.0f;
    g_P2[(size_t)(b * (NSEQ + 1)) * DDIM + d] = 0.0f;
#pragma unroll 4
    for (int p = 0; p < NSEQ; p++) {
        int   r  = g_perm[b * NSEQ + p];
        float w1 = g_E1[b * NSEQ + p];
        float w2 = g_E2[b * NSEQ + p];
        float v  = vwb[(size_t)r * DDIM + d];
        a0 += v; a1 += w1 * v; a2 += w2 * v;
        g_P1[(size_t)(b * (NSEQ + 1) + p + 1) * DDIM + d] = a1;
        g_P2[(size_t)(b * (NSEQ + 1) + p + 1) * DDIM + d] = a2;
    }
    g_vsum[b * DDIM + d] = a0;
}

// ---------------- output: binary search + combine + bias ------------------
// one block per output row i (16384 blocks, 256 threads, 4 floats/thread)
__global__ void __launch_bounds__(256) out_kernel(const float* __restrict__ bo,
                                                  float* __restrict__ out) {
    const int i = blockIdx.x;
    const int b = i >> 11;
    const float tq = g_tQ[i];
    const float* ks = g_tKs + b * NSEQ;
    int lo = 0, hi = NSEQ;
    while (lo < hi) {                 // upper_bound: count of tK <= tQ
        int mid = (lo + hi) >> 1;
        if (ks[mid] <= tq) lo = mid + 1; else hi = mid;
    }
    const int r = lo;
    const float e2  = expf( 2.0f * tq);
    const float em2 = expf(-2.0f * tq);
    const int d = threadIdx.x * 4;
    const float4 p1  = *(const float4*)(g_P1 + (size_t)(b * (NSEQ + 1) + r)    * DDIM + d);
    const float4 p2  = *(const float4*)(g_P2 + (size_t)(b * (NSEQ + 1) + r)    * DDIM + d);
    const float4 p2t = *(const float4*)(g_P2 + (size_t)(b * (NSEQ + 1) + NSEQ) * DDIM + d);
    const float4 vs  = *(const float4*)(g_vsum + (size_t)b * DDIM + d);
    const float4 bb  = *(const float4*)(bo + d);
    const float A_STDP = 0.9f, W_OFF = 0.9f;
    float4 o;
    o.x = A_STDP * (e2 * (p2t.x - p2.x) - em2 * p1.x) + W_OFF * vs.x + bb.x;
    o.y = A_STDP * (e2 * (p2t.y - p2.y) - em2 * p1.y) + W_OFF * vs.y + bb.y;
    o.z = A_STDP * (e2 * (p2t.z - p2.z) - em2 * p1.z) + W_OFF * vs.z + bb.z;
    o.w = A_STDP * (e2 * (p2t.w - p2.w) - em2 * p1.w) + W_OFF * vs.w + bb.w;
    *(float4*)(out + (size_t)i * DDIM + d) = o;
}

// ---------------------------------------------------------------------------
extern "C" void kernel_launch(void* const* d_in, const int* in_sizes, int n_in,
                              void* d_out, int out_size) {
    const float* x  = (const float*)d_in[0];
    const float* Wq = (const float*)d_in[1];
    const float* gq = (const float*)d_in[2];
    const float* bq = (const float*)d_in[3];
    const float* mq = (const float*)d_in[4];
    const float* vq = (const float*)d_in[5];
    const float* Wk = (const float*)d_in[6];
    const float* gk = (const float*)d_in[7];
    const float* bk = (const float*)d_in[8];
    const float* mk = (const float*)d_in[9];
    const float* vk = (const float*)d_in[10];
    const float* Wv = (const float*)d_in[11];
    const float* gv = (const float*)d_in[12];
    const float* bv = (const float*)d_in[13];
    const float* mv = (const float*)d_in[14];
    const float* vv = (const float*)d_in[15];
    const float* Wo = (const float*)d_in[16];
    const float* bo = (const float*)d_in[17];
    float* out = (float*)d_out;

    dim3 gg(8, 128);   // (col tiles, row tiles)
    gemm_kernel<0><<<gg, 256>>>(x, Wq, mq, gq, vq, bq, 0);   // Q row-sums
    gemm_kernel<0><<<gg, 256>>>(x, Wk, mk, gk, vk, bk, 1);   // K row-sums
    gemm_kernel<1><<<gg, 256>>>(x, Wv, mv, gv, vv, bv, 0);   // V
    gemm_kernel<2><<<gg, 256>>>(nullptr, Wo, nullptr, nullptr, nullptr, nullptr, 0); // VW = V@Wo

    reduce_t_kernel<<<64, 256>>>();
    sort_kernel<<<NBATCH, 1024>>>();
    scan_kernel<<<dim3(16, NBATCH), 64>>>();
    out_kernel<<<MROWS, 256>>>(bo, out);
}

// round 4
// speedup vs baseline: 1.0004x; 1.0004x over previous
#include <cuda_runtime.h>
#include <math.h>

// Problem dims
#define MROWS 16384   // B*N
#define DDIM  1024
#define NSEQ  2048
#define NBATCH 8

// ---------------- scratch (device globals; no allocations allowed) --------
__device__ float g_V [MROWS * DDIM];            // sigmoid(bn(x@Wv))       64MB
__device__ float g_VW[MROWS * DDIM];            // V @ Wo                  64MB
__device__ float g_P1[NBATCH * (NSEQ + 1) * DDIM]; // prefix e^{+2tK}*VW   67MB
__device__ float g_P2[NBATCH * (NSEQ + 1) * DDIM]; // prefix e^{-2tK}*VW   67MB
__device__ float g_qpart[MROWS * 8];
__device__ float g_kpart[MROWS * 8];
__device__ float g_tQ[MROWS];
__device__ float g_tK[MROWS];
__device__ float g_tKs[NBATCH * NSEQ];          // sorted tK per batch
__device__ float g_E1 [NBATCH * NSEQ];          // e^{+2 tKs}
__device__ float g_E2 [NBATCH * NSEQ];          // e^{-2 tKs}
__device__ int   g_perm[NBATCH * NSEQ];         // sort permutation
__device__ float g_vsum[NBATCH * DDIM];         // unweighted colsum of VW

// ---------------- packed f32x2 helpers ------------------------------------
__device__ __forceinline__ unsigned long long pk2(float x, float y) {
    unsigned long long r;
    asm("mov.b64 %0, {%1, %2};" : "=l"(r) : "f"(x), "f"(y));
    return r;
}
__device__ __forceinline__ void upk2(unsigned long long v, float& x, float& y) {
    asm("mov.b64 {%0, %1}, %2;" : "=f"(x), "=f"(y) : "l"(v));
}
__device__ __forceinline__ void fma2(unsigned long long& c,
                                     unsigned long long a, unsigned long long b) {
    asm("fma.rn.f32x2 %0, %1, %2, %0;" : "+l"(c) : "l"(a), "l"(b));
}

// ---------------- GEMM: 128x128 tile, K-step 16, 8x8 per thread -----------
// MODE 0: bn+sigmoid epilogue, per-row partial sums -> g_qpart/g_kpart
// MODE 1: bn+sigmoid epilogue, write g_V
// MODE 2: plain GEMM of g_V @ Bm -> g_VW
template <int MODE>
__global__ void __launch_bounds__(256)
gemm_kernel(const float* __restrict__ A, const float* __restrict__ Bm,
            const float* __restrict__ mean, const float* __restrict__ gam,
            const float* __restrict__ var, const float* __restrict__ beta,
            int which)
{
    __shared__ float As[16][128];
    __shared__ float Bs[16][128];
    __shared__ float red[128][17];

    const int tid = threadIdx.x;
    const int bc = blockIdx.x;   // 0..7   (col tile)
    const int br = blockIdx.y;   // 0..127 (row tile)
    const int tx = tid & 15, ty = tid >> 4;
    const float* Ap = (MODE == 2) ? g_V : A;

    unsigned long long c[8][4];
#pragma unroll
    for (int i = 0; i < 8; i++)
#pragma unroll
        for (int j = 0; j < 4; j++) c[i][j] = 0ull;

    for (int kb = 0; kb < DDIM; kb += 16) {
#pragma unroll
        for (int l = 0; l < 2; l++) {
            int idx = tid + l * 256;              // 0..511 float4 slots
            int arow = idx >> 2, akq = (idx & 3) << 2;
            float4 va = *(const float4*)(Ap + (size_t)(br * 128 + arow) * DDIM + kb + akq);
            As[akq + 0][arow] = va.x; As[akq + 1][arow] = va.y;
            As[akq + 2][arow] = va.z; As[akq + 3][arow] = va.w;
            int krow = idx >> 5, nq = idx & 31;
            *(float4*)&Bs[krow][nq << 2] =
                *(const float4*)(Bm + (size_t)(kb + krow) * DDIM + bc * 128 + (nq << 2));
        }
        __syncthreads();
#pragma unroll
        for (int kk = 0; kk < 16; kk++) {
            float4 a0 = *(const float4*)&As[kk][ty * 8];
            float4 a1 = *(const float4*)&As[kk][ty * 8 + 4];
            float4 b0 = *(const float4*)&Bs[kk][tx * 8];
            float4 b1 = *(const float4*)&Bs[kk][tx * 8 + 4];
            unsigned long long bb0 = pk2(b0.x, b0.y), bb1 = pk2(b0.z, b0.w);
            unsigned long long bb2 = pk2(b1.x, b1.y), bb3 = pk2(b1.z, b1.w);
            float av[8] = {a0.x, a0.y, a0.z, a0.w, a1.x, a1.y, a1.z, a1.w};
#pragma unroll
            for (int i = 0; i < 8; i++) {
                unsigned long long aa = pk2(av[i], av[i]);
                fma2(c[i][0], aa, bb0); fma2(c[i][1], aa, bb1);
                fma2(c[i][2], aa, bb2); fma2(c[i][3], aa, bb3);
            }
        }
        __syncthreads();
    }

    const int col0 = bc * 128 + tx * 8;
    const int row0 = br * 128 + ty * 8;

    if (MODE == 2) {
#pragma unroll
        for (int i = 0; i < 8; i++) {
            float v0, v1, v2, v3, v4, v5, v6, v7;
            upk2(c[i][0], v0, v1); upk2(c[i][1], v2, v3);
            upk2(c[i][2], v4, v5); upk2(c[i][3], v6, v7);
            float4 o0 = make_float4(v0, v1, v2, v3);
            float4 o1 = make_float4(v4, v5, v6, v7);
            *(float4*)(g_VW + (size_t)(row0 + i) * DDIM + col0)     = o0;
            *(float4*)(g_VW + (size_t)(row0 + i) * DDIM + col0 + 4) = o1;
        }
    } else {
        float mm[8], sc[8], bt[8];
#pragma unroll
        for (int j = 0; j < 8; j++) {
            mm[j] = mean[col0 + j];
            sc[j] = gam[col0 + j] * rsqrtf(var[col0 + j] + 1e-5f);
            bt[j] = beta[col0 + j];
        }
#pragma unroll
        for (int i = 0; i < 8; i++) {
            float raw[8];
            upk2(c[i][0], raw[0], raw[1]); upk2(c[i][1], raw[2], raw[3]);
            upk2(c[i][2], raw[4], raw[5]); upk2(c[i][3], raw[6], raw[7]);
            float val[8];
#pragma unroll
            for (int j = 0; j < 8; j++) {
                float h = (raw[j] - mm[j]) * sc[j] + bt[j];
                // sigmoid(4*(h-1)) = 1/(1+exp(4-4h))
                val[j] = 1.0f / (1.0f + __expf(4.0f - 4.0f * h));
            }
            if (MODE == 1) {
                float4 o0 = make_float4(val[0], val[1], val[2], val[3]);
                float4 o1 = make_float4(val[4], val[5], val[6], val[7]);
                *(float4*)(g_V + (size_t)(row0 + i) * DDIM + col0)     = o0;
                *(float4*)(g_V + (size_t)(row0 + i) * DDIM + col0 + 4) = o1;
            } else {
                float s = 0.0f;
#pragma unroll
                for (int j = 0; j < 8; j++) s += val[j];
                red[ty * 8 + i][tx] = s;
            }
        }
        if (MODE == 0) {
            __syncthreads();
            if (tid < 128) {
                float s = 0.0f;
#pragma unroll
                for (int j = 0; j < 16; j++) s += red[tid][j];
                float* part = which ? g_kpart : g_qpart;
                part[(size_t)(br * 128 + tid) * 8 + bc] = s;   // deterministic
            }
        }
    }
}

// ---------------- t = 1 - mean --------------------------------------------
__global__ void reduce_t_kernel() {
    int i = blockIdx.x * blockDim.x + threadIdx.x;
    if (i < MROWS) {
        float sq = 0.0f, sk = 0.0f;
#pragma unroll
        for (int j = 0; j < 8; j++) { sq += g_qpart[i * 8 + j]; sk += g_kpart[i * 8 + j]; }
        g_tQ[i] = 1.0f - sq * (1.0f / 1024.0f);
        g_tK[i] = 1.0f - sk * (1.0f / 1024.0f);
    }
}

// ---------------- bitonic sort of tK per batch (2048 elems) ---------------
__global__ void __launch_bounds__(1024) sort_kernel() {
    __shared__ float sv[NSEQ];
    __shared__ int   si[NSEQ];
    const int b = blockIdx.x, t = threadIdx.x;
    sv[t]        = g_tK[b * NSEQ + t];        si[t]        = t;
    sv[t + 1024] = g_tK[b * NSEQ + t + 1024]; si[t + 1024] = t + 1024;
    __syncthreads();
    for (int k = 2; k <= NSEQ; k <<= 1) {
        for (int j = k >> 1; j > 0; j >>= 1) {
#pragma unroll
            for (int l = 0; l < 2; l++) {
                int idx = t + l * 1024;
                int ixj = idx ^ j;
                if (ixj > idx) {
                    bool asc = ((idx & k) == 0);
                    float a = sv[idx], bvv = sv[ixj];
                    if ((a > bvv) == asc) {
                        sv[idx] = bvv; sv[ixj] = a;
                        int tmp = si[idx]; si[idx] = si[ixj]; si[ixj] = tmp;
                    }
                }
            }
            __syncthreads();
        }
    }
#pragma unroll
    for (int l = 0; l < 2; l++) {
        int idx = t + l * 1024;
        float tk = sv[idx];
        g_tKs [b * NSEQ + idx] = tk;
        g_perm[b * NSEQ + idx] = si[idx];
        g_E1  [b * NSEQ + idx] = expf( 2.0f * tk);
        g_E2  [b * NSEQ + idx] = expf(-2.0f * tk);
    }
}

// ---------------- weighted prefix sums over VW rows in sorted order -------
// grid (16, 8), 64 threads: block covers batch=by, d-range [bx*64, bx*64+64)
__global__ void __launch_bounds__(64) scan_kernel() {
    const int b  = blockIdx.y;
    const int d  = blockIdx.x * 64 + threadIdx.x;
    const float* vwb = g_VW + (size_t)b * NSEQ * DDIM;
    float a0 = 0.0f, a1 = 0.0f, a2 = 0.0f;
    g_P1[(size_t)(b * (NSEQ + 1)) * DDIM + d] = 0.0f;
    g_P2[(size_t)(b * (NSEQ + 1)) * DDIM + d] = 0.0f;
#pragma unroll 4
    for (int p = 0; p < NSEQ; p++) {
        int   r  = g_perm[b * NSEQ + p];
        float w1 = g_E1[b * NSEQ + p];
        float w2 = g_E2[b * NSEQ + p];
        float v  = vwb[(size_t)r * DDIM + d];
        a0 += v; a1 += w1 * v; a2 += w2 * v;
        g_P1[(size_t)(b * (NSEQ + 1) + p + 1) * DDIM + d] = a1;
        g_P2[(size_t)(b * (NSEQ + 1) + p + 1) * DDIM + d] = a2;
    }
    g_vsum[b * DDIM + d] = a0;
}

// ---------------- output: binary search + combine + bias ------------------
// one block per output row i (16384 blocks, 256 threads, 4 floats/thread)
__global__ void __launch_bounds__(256) out_kernel(const float* __restrict__ bo,
                                                  float* __restrict__ out) {
    const int i = blockIdx.x;
    const int b = i >> 11;
    const float tq = g_tQ[i];
    const float* ks = g_tKs + b * NSEQ;
    int lo = 0, hi = NSEQ;
    while (lo < hi) {                 // upper_bound: count of tK <= tQ
        int mid = (lo + hi) >> 1;
        if (ks[mid] <= tq) lo = mid + 1; else hi = mid;
    }
    const int r = lo;
    const float e2  = expf( 2.0f * tq);
    const float em2 = expf(-2.0f * tq);
    const int d = threadIdx.x * 4;
    const float4 p1  = *(const float4*)(g_P1 + (size_t)(b * (NSEQ + 1) + r)    * DDIM + d);
    const float4 p2  = *(const float4*)(g_P2 + (size_t)(b * (NSEQ + 1) + r)    * DDIM + d);
    const float4 p2t = *(const float4*)(g_P2 + (size_t)(b * (NSEQ + 1) + NSEQ) * DDIM + d);
    const float4 vs  = *(const float4*)(g_vsum + (size_t)b * DDIM + d);
    const float4 bb  = *(const float4*)(bo + d);
    const float A_STDP = 0.9f, W_OFF = 0.9f;
    float4 o;
    o.x = A_STDP * (e2 * (p2t.x - p2.x) - em2 * p1.x) + W_OFF * vs.x + bb.x;
    o.y = A_STDP * (e2 * (p2t.y - p2.y) - em2 * p1.y) + W_OFF * vs.y + bb.y;
    o.z = A_STDP * (e2 * (p2t.z - p2.z) - em2 * p1.z) + W_OFF * vs.z + bb.z;
    o.w = A_STDP * (e2 * (p2t.w - p2.w) - em2 * p1.w) + W_OFF * vs.w + bb.w;
    *(float4*)(out + (size_t)i * DDIM + d) = o;
}

// ---------------------------------------------------------------------------
extern "C" void kernel_launch(void* const* d_in, const int* in_sizes, int n_in,
                              void* d_out, int out_size) {
    const float* x  = (const float*)d_in[0];
    const float* Wq = (const float*)d_in[1];
    const float* gq = (const float*)d_in[2];
    const float* bq = (const float*)d_in[3];
    const float* mq = (const float*)d_in[4];
    const float* vq = (const float*)d_in[5];
    const float* Wk = (const float*)d_in[6];
    const float* gk = (const float*)d_in[7];
    const float* bk = (const float*)d_in[8];
    const float* mk = (const float*)d_in[9];
    const float* vk = (const float*)d_in[10];
    const float* Wv = (const float*)d_in[11];
    const float* gv = (const float*)d_in[12];
    const float* bv = (const float*)d_in[13];
    const float* mv = (const float*)d_in[14];
    const float* vv = (const float*)d_in[15];
    const float* Wo = (const float*)d_in[16];
    const float* bo = (const float*)d_in[17];
    float* out = (float*)d_out;

    dim3 gg(8, 128);   // (col tiles, row tiles)
    gemm_kernel<0><<<gg, 256>>>(x, Wq, mq, gq, vq, bq, 0);   // Q row-sums
    gemm_kernel<0><<<gg, 256>>>(x, Wk, mk, gk, vk, bk, 1);   // K row-sums
    gemm_kernel<1><<<gg, 256>>>(x, Wv, mv, gv, vv, bv, 0);   // V
    gemm_kernel<2><<<gg, 256>>>(nullptr, Wo, nullptr, nullptr, nullptr, nullptr, 0); // VW = V@Wo

    reduce_t_kernel<<<64, 256>>>();
    sort_kernel<<<NBATCH, 1024>>>();
    scan_kernel<<<dim3(16, NBATCH), 64>>>();
    out_kernel<<<MROWS, 256>>>(bo, out);
}

// round 7
// speedup vs baseline: 2.5719x; 2.5707x over previous
#include <cuda_runtime.h>
#include <cuda_bf16.h>
#include <stdint.h>
#include <math.h>

#define MROWS 16384   // B*N
#define DDIM  1024
#define NSEQ  2048
#define NBATCH 8
#define NSEG  32
#define SEGLEN 64     // NSEQ / NSEG

// ---------------- scratch (device globals) ---------------------------------
__device__ __nv_bfloat16 g_xhi[MROWS * DDIM];
__device__ __nv_bfloat16 g_xlo[MROWS * DDIM];
__device__ __nv_bfloat16 g_WThi[4 * DDIM * DDIM];   // transposed weights [n][k]
__device__ __nv_bfloat16 g_WTlo[4 * DDIM * DDIM];
__device__ __nv_bfloat16 g_Vhi[MROWS * DDIM];
__device__ __nv_bfloat16 g_Vlo[MROWS * DDIM];
__device__ float g_VW[MROWS * DDIM];
__device__ float g_P1[NBATCH * (NSEQ + 1) * DDIM];
__device__ float g_P2[NBATCH * (NSEQ + 1) * DDIM];
__device__ float g_qpart[MROWS * 8];
__device__ float g_kpart[MROWS * 8];
__device__ float g_tQ[MROWS];
__device__ float g_tK[MROWS];
__device__ float g_tKs[NBATCH * NSEQ];
__device__ float g_E1[NBATCH * NSEQ];
__device__ float g_E2[NBATCH * NSEQ];
__device__ int   g_perm[NBATCH * NSEQ];
__device__ float g_vsum[NBATCH * DDIM];
__device__ float g_s0[NBATCH * NSEG * DDIM];
__device__ float g_s1[NBATCH * NSEG * DDIM];
__device__ float g_s2[NBATCH * NSEG * DDIM];

// ---------------- PTX helpers (base sm_103 target only!) -------------------
__device__ __forceinline__ uint32_t smem_u32(const void* p) {
    uint32_t a;
    asm("{ .reg .u64 t; cvta.to.shared.u64 t, %1; cvt.u32.u64 %0, t; }"
        : "=r"(a) : "l"(p));
    return a;
}
__device__ __forceinline__ void ldsm4(uint32_t* r, uint32_t a) {
    asm volatile("ldmatrix.sync.aligned.m8n8.x4.shared.b16 {%0,%1,%2,%3}, [%4];"
        : "=r"(r[0]), "=r"(r[1]), "=r"(r[2]), "=r"(r[3]) : "r"(a));
}
__device__ __forceinline__ void mma16816(float* c, const uint32_t* a, const uint32_t* b) {
    asm volatile("mma.sync.aligned.m16n8k16.row.col.f32.bf16.bf16.f32 "
        "{%0,%1,%2,%3},{%4,%5,%6,%7},{%8,%9},{%0,%1,%2,%3};"
        : "+f"(c[0]), "+f"(c[1]), "+f"(c[2]), "+f"(c[3])
        : "r"(a[0]), "r"(a[1]), "r"(a[2]), "r"(a[3]), "r"(b[0]), "r"(b[1]));
}
__device__ __forceinline__ void cpa16(uint32_t dst, const void* src) {
    asm volatile("cp.async.cg.shared.global [%0], [%1], 16;" :: "r"(dst), "l"(src));
}
__device__ __forceinline__ uint32_t bf2(float a, float b) {
    __nv_bfloat162 t = __floats2bfloat162_rn(a, b);
    return *reinterpret_cast<uint32_t*>(&t);
}

// ---------------- prep: x -> bf16 hi/lo -------------------------------------
__global__ void __launch_bounds__(256) prep_x(const float* __restrict__ x) {
    size_t i = ((size_t)blockIdx.x * 256 + threadIdx.x) * 4;
    float4 v = *(const float4*)(x + i);
    float h0 = __bfloat162float(__float2bfloat16(v.x));
    float h1 = __bfloat162float(__float2bfloat16(v.y));
    float h2 = __bfloat162float(__float2bfloat16(v.z));
    float h3 = __bfloat162float(__float2bfloat16(v.w));
    uint2 hi = make_uint2(bf2(h0, h1), bf2(h2, h3));
    uint2 lo = make_uint2(bf2(v.x - h0, v.y - h1), bf2(v.z - h2, v.w - h3));
    *(uint2*)(g_xhi + i) = hi;
    *(uint2*)(g_xlo + i) = lo;
}

// ---------------- prep: transpose W -> bf16 hi/lo [n][k] ---------------------
__global__ void __launch_bounds__(256) prep_w(const float* W0, const float* W1,
                                              const float* W2, const float* W3) {
    __shared__ float t[32][33];
    const float* W = blockIdx.z == 0 ? W0 : blockIdx.z == 1 ? W1
                   : blockIdx.z == 2 ? W2 : W3;
    __nv_bfloat16* oh = g_WThi + (size_t)blockIdx.z * DDIM * DDIM;
    __nv_bfloat16* ol = g_WTlo + (size_t)blockIdx.z * DDIM * DDIM;
    int n0 = blockIdx.x * 32, k0 = blockIdx.y * 32;
    int tx = threadIdx.x, ty = threadIdx.y;       // 32 x 8
#pragma unroll
    for (int j = 0; j < 4; j++)
        t[ty + j * 8][tx] = W[(size_t)(k0 + ty + j * 8) * DDIM + n0 + tx];
    __syncthreads();
#pragma unroll
    for (int j = 0; j < 4; j++) {
        int nn = ty + j * 8;
        float v = t[tx][nn];                      // = W[k0+tx][n0+nn]
        __nv_bfloat16 h = __float2bfloat16(v);
        oh[(size_t)(n0 + nn) * DDIM + k0 + tx] = h;
        ol[(size_t)(n0 + nn) * DDIM + k0 + tx] =
            __float2bfloat16(v - __bfloat162float(h));
    }
}

// ---------------- HMMA GEMM: 128x128 tile, BK=32, 3x bf16 split -------------
// MODE 0: BN+sigmoid epilogue -> per-row partial sums into `part`
// MODE 1: BN+sigmoid epilogue -> g_Vhi/g_Vlo (bf16 split)
// MODE 2: plain epilogue -> g_VW (fp32)
#define AROW 80                       // padded row bytes (32 bf16 -> 80B, bank-clean)
#define TILEB (128 * AROW)            // 10240
#define STAGE (4 * TILEB)             // 40960  (Ah, Al, Bh, Bl)
#define BN_OFF (2 * STAGE)            // 81920
#define RED_OFF (BN_OFF + 3 * 128 * 4)
#define GEMM_SMEM (RED_OFF + 256 * 4) // 84480

__device__ __forceinline__ void ld_tile(uint32_t sm, const __nv_bfloat16* __restrict__ src,
                                        int r0, int kb, int tid) {
#pragma unroll
    for (int i = 0; i < 2; i++) {
        int idx = i * 256 + tid;          // 0..511
        int row = idx >> 2, c = idx & 3;
        cpa16(sm + row * AROW + c * 16,
              src + (size_t)(r0 + row) * DDIM + kb + c * 8);
    }
}

template <int MODE>
__global__ void __launch_bounds__(256, 1)
tc_gemm(const __nv_bfloat16* __restrict__ Ahi, const __nv_bfloat16* __restrict__ Alo,
        const __nv_bfloat16* __restrict__ Bhi, const __nv_bfloat16* __restrict__ Blo,
        const float* __restrict__ mean, const float* __restrict__ gam,
        const float* __restrict__ var, const float* __restrict__ beta,
        float* __restrict__ part)
{
    extern __shared__ char smem[];
    const uint32_t sb = smem_u32(smem);
    const int tid = threadIdx.x, lane = tid & 31, wid = tid >> 5;
    const int wm = wid & 3, wn = wid >> 2;        // 4 (M) x 2 (N) warps
    const int bc = blockIdx.x, br = blockIdx.y;
    const int row0 = br * 128, col0 = bc * 128;

    float* pm = (float*)(smem + BN_OFF);
    float* ps = pm + 128;
    float* pb = ps + 128;
    if (MODE != 2 && tid < 128) {
        pm[tid] = mean[col0 + tid];
        ps[tid] = gam[col0 + tid] * rsqrtf(var[col0 + tid] + 1e-5f);
        pb[tid] = beta[col0 + tid];
    }

    float acc[2][8][4];
#pragma unroll
    for (int a = 0; a < 2; a++)
#pragma unroll
        for (int b = 0; b < 8; b++)
#pragma unroll
            for (int q = 0; q < 4; q++) acc[a][b][q] = 0.0f;

    // prefetch kb=0 into stage 0
    ld_tile(sb + 0 * TILEB, Ahi, row0, 0, tid);
    ld_tile(sb + 1 * TILEB, Alo, row0, 0, tid);
    ld_tile(sb + 2 * TILEB, Bhi, col0, 0, tid);
    ld_tile(sb + 3 * TILEB, Blo, col0, 0, tid);
    asm volatile("cp.async.commit_group;" ::: "memory");

    for (int kb = 0; kb < 32; kb++) {
        const uint32_t st = sb + (kb & 1) * STAGE;
        if (kb < 31) {
            const uint32_t nst = sb + ((kb + 1) & 1) * STAGE;
            const int k = (kb + 1) * 32;
            ld_tile(nst + 0 * TILEB, Ahi, row0, k, tid);
            ld_tile(nst + 1 * TILEB, Alo, row0, k, tid);
            ld_tile(nst + 2 * TILEB, Bhi, col0, k, tid);
            ld_tile(nst + 3 * TILEB, Blo, col0, k, tid);
            asm volatile("cp.async.commit_group;" ::: "memory");
            asm volatile("cp.async.wait_group 1;" ::: "memory");
        } else {
            asm volatile("cp.async.wait_group 0;" ::: "memory");
        }
        __syncthreads();

        const uint32_t Ah = st, Al = st + TILEB, Bh = st + 2 * TILEB, Bl = st + 3 * TILEB;
#pragma unroll
        for (int s = 0; s < 2; s++) {                 // two k16 steps in BK=32
            uint32_t ah[2][4], al[2][4];
#pragma unroll
            for (int mi = 0; mi < 2; mi++) {
                uint32_t ao = (uint32_t)((wm * 32 + mi * 16 + (lane & 15)) * AROW
                                         + (2 * s + (lane >> 4)) * 16);
                ldsm4(ah[mi], Ah + ao);
                ldsm4(al[mi], Al + ao);
            }
#pragma unroll
            for (int j = 0; j < 4; j++) {
                uint32_t bo = (uint32_t)((wn * 64 + j * 16 + (lane & 7) + ((lane >> 4) << 3)) * AROW
                                         + (2 * s + ((lane >> 3) & 1)) * 16);
                uint32_t bh[4], bl[4];
                ldsm4(bh, Bh + bo);
                ldsm4(bl, Bl + bo);
#pragma unroll
                for (int mi = 0; mi < 2; mi++)
#pragma unroll
                    for (int t = 0; t < 2; t++) {
                        mma16816(acc[mi][j * 2 + t], ah[mi], &bh[t * 2]);
                        mma16816(acc[mi][j * 2 + t], ah[mi], &bl[t * 2]);
                        mma16816(acc[mi][j * 2 + t], al[mi], &bh[t * 2]);
                    }
            }
        }
        __syncthreads();
    }

    // ---------------- epilogue ------------------------------------------------
    // thread's elements: rows (row0 + wm*32 + mi*16 + lane/4 + {0,8}),
    //                    cols (col0 + wn*64 + ni*8 + (lane&3)*2 + {0,1})
    if (MODE == 0) {
        float* red = (float*)(smem + RED_OFF);
        float s[2][2] = {{0.f, 0.f}, {0.f, 0.f}};
#pragma unroll
        for (int mi = 0; mi < 2; mi++)
#pragma unroll
            for (int ni = 0; ni < 8; ni++) {
                int cl = wn * 64 + ni * 8 + (lane & 3) * 2;
                float m0 = pm[cl], m1 = pm[cl + 1];
                float c0 = ps[cl], c1 = ps[cl + 1];
                float b0 = pb[cl], b1 = pb[cl + 1];
                float h;
                h = (acc[mi][ni][0] - m0) * c0 + b0; s[mi][0] += 1.f / (1.f + __expf(4.f - 4.f * h));
                h = (acc[mi][ni][1] - m1) * c1 + b1; s[mi][0] += 1.f / (1.f + __expf(4.f - 4.f * h));
                h = (acc[mi][ni][2] - m0) * c0 + b0; s[mi][1] += 1.f / (1.f + __expf(4.f - 4.f * h));
                h = (acc[mi][ni][3] - m1) * c1 + b1; s[mi][1] += 1.f / (1.f + __expf(4.f - 4.f * h));
            }
#pragma unroll
        for (int mi = 0; mi < 2; mi++)
#pragma unroll
            for (int hh = 0; hh < 2; hh++) {
                float v = s[mi][hh];
                v += __shfl_xor_sync(0xffffffffu, v, 1);
                v += __shfl_xor_sync(0xffffffffu, v, 2);
                if ((lane & 3) == 0)
                    red[wn * 128 + wm * 32 + mi * 16 + hh * 8 + (lane >> 2)] = v;
            }
        __syncthreads();
        if (tid < 128)
            part[(size_t)(row0 + tid) * 8 + bc] = red[tid] + red[128 + tid];
    } else if (MODE == 1) {
#pragma unroll
        for (int mi = 0; mi < 2; mi++) {
            int r = row0 + wm * 32 + mi * 16 + (lane >> 2);
#pragma unroll
            for (int ni = 0; ni < 8; ni++) {
                int cl = wn * 64 + ni * 8 + (lane & 3) * 2;
                int col = col0 + cl;
#pragma unroll
                for (int p = 0; p < 2; p++) {
                    float h0 = (acc[mi][ni][p * 2 + 0] - pm[cl]) * ps[cl] + pb[cl];
                    float h1 = (acc[mi][ni][p * 2 + 1] - pm[cl + 1]) * ps[cl + 1] + pb[cl + 1];
                    float v0 = 1.f / (1.f + __expf(4.f - 4.f * h0));
                    float v1 = 1.f / (1.f + __expf(4.f - 4.f * h1));
                    float g0 = __bfloat162float(__float2bfloat16(v0));
                    float g1 = __bfloat162float(__float2bfloat16(v1));
                    size_t off = (size_t)(r + p * 8) * DDIM + col;
                    *(uint32_t*)(g_Vhi + off) = bf2(g0, g1);
                    *(uint32_t*)(g_Vlo + off) = bf2(v0 - g0, v1 - g1);
                }
            }
        }
    } else {
#pragma unroll
        for (int mi = 0; mi < 2; mi++) {
            int r = row0 + wm * 32 + mi * 16 + (lane >> 2);
#pragma unroll
            for (int ni = 0; ni < 8; ni++) {
                int col = col0 + wn * 64 + ni * 8 + (lane & 3) * 2;
                *(float2*)(g_VW + (size_t)r * DDIM + col) =
                    make_float2(acc[mi][ni][0], acc[mi][ni][1]);
                *(float2*)(g_VW + (size_t)(r + 8) * DDIM + col) =
                    make_float2(acc[mi][ni][2], acc[mi][ni][3]);
            }
        }
    }
}

// ---------------- t = 1 - mean ----------------------------------------------
__global__ void reduce_t_kernel() {
    int i = blockIdx.x * blockDim.x + threadIdx.x;
    if (i < MROWS) {
        float sq = 0.0f, sk = 0.0f;
#pragma unroll
        for (int j = 0; j < 8; j++) { sq += g_qpart[i * 8 + j]; sk += g_kpart[i * 8 + j]; }
        g_tQ[i] = 1.0f - sq * (1.0f / 1024.0f);
        g_tK[i] = 1.0f - sk * (1.0f / 1024.0f);
    }
}

// ---------------- bitonic sort of tK per batch -------------------------------
__global__ void __launch_bounds__(1024) sort_kernel() {
    __shared__ float sv[NSEQ];
    __shared__ int   si[NSEQ];
    const int b = blockIdx.x, t = threadIdx.x;
    sv[t]        = g_tK[b * NSEQ + t];        si[t]        = t;
    sv[t + 1024] = g_tK[b * NSEQ + t + 1024]; si[t + 1024] = t + 1024;
    __syncthreads();
    for (int k = 2; k <= NSEQ; k <<= 1) {
        for (int j = k >> 1; j > 0; j >>= 1) {
#pragma unroll
            for (int l = 0; l < 2; l++) {
                int idx = t + l * 1024;
                int ixj = idx ^ j;
                if (ixj > idx) {
                    bool asc = ((idx & k) == 0);
                    float a = sv[idx], bvv = sv[ixj];
                    if ((a > bvv) == asc) {
                        sv[idx] = bvv; sv[ixj] = a;
                        int tmp = si[idx]; si[idx] = si[ixj]; si[ixj] = tmp;
                    }
                }
            }
            __syncthreads();
        }
    }
#pragma unroll
    for (int l = 0; l < 2; l++) {
        int idx = t + l * 1024;
        float tk = sv[idx];
        g_tKs [b * NSEQ + idx] = tk;
        g_perm[b * NSEQ + idx] = si[idx];
        g_E1  [b * NSEQ + idx] = expf( 2.0f * tk);
        g_E2  [b * NSEQ + idx] = expf(-2.0f * tk);
    }
}

// ---------------- segmented scan: pass A (per-segment totals) ---------------
__global__ void __launch_bounds__(1024) scanA_kernel() {
    const int seg = blockIdx.x, b = blockIdx.y, d = threadIdx.x;
    const int base = b * NSEQ + seg * SEGLEN;
    float a0 = 0.0f, a1 = 0.0f, a2 = 0.0f;
#pragma unroll 4
    for (int p = 0; p < SEGLEN; p++) {
        int   r  = g_perm[base + p];
        float w1 = g_E1[base + p];
        float w2 = g_E2[base + p];
        float v  = g_VW[((size_t)b * NSEQ + r) * DDIM + d];
        a0 += v; a1 += w1 * v; a2 += w2 * v;
    }
    size_t o = ((size_t)(b * NSEG + seg)) * DDIM + d;
    g_s0[o] = a0; g_s1[o] = a1; g_s2[o] = a2;
}

// ---------------- pass B: exclusive offsets across segments -----------------
__global__ void __launch_bounds__(1024) scanB_kernel() {
    const int b = blockIdx.x, d = threadIdx.x;
    float o0 = 0.0f, o1 = 0.0f, o2 = 0.0f;
#pragma unroll 4
    for (int s = 0; s < NSEG; s++) {
        size_t i = ((size_t)(b * NSEG + s)) * DDIM + d;
        float t0 = g_s0[i], t1 = g_s1[i], t2 = g_s2[i];
        g_s1[i] = o1; g_s2[i] = o2;          // overwrite with exclusive offsets
        o0 += t0; o1 += t1; o2 += t2;
    }
    g_vsum[b * DDIM + d] = o0;
}

// ---------------- pass C: local scan + offset -> P1/P2 ----------------------
__global__ void __launch_bounds__(1024) scanC_kernel() {
    const int seg = blockIdx.x, b = blockIdx.y, d = threadIdx.x;
    const int base = b * NSEQ + seg * SEGLEN;
    size_t so = ((size_t)(b * NSEG + seg)) * DDIM + d;
    float a1 = g_s1[so], a2 = g_s2[so];
    if (seg == 0) {
        g_P1[((size_t)b * (NSEQ + 1)) * DDIM + d] = 0.0f;
        g_P2[((size_t)b * (NSEQ + 1)) * DDIM + d] = 0.0f;
    }
#pragma unroll 4
    for (int p = 0; p < SEGLEN; p++) {
        int   r  = g_perm[base + p];
        float w1 = g_E1[base + p];
        float w2 = g_E2[base + p];
        float v  = g_VW[((size_t)b * NSEQ + r) * DDIM + d];
        a1 += w1 * v; a2 += w2 * v;
        size_t po = ((size_t)b * (NSEQ + 1) + seg * SEGLEN + p + 1) * DDIM + d;
        g_P1[po] = a1; g_P2[po] = a2;
    }
}

// ---------------- output: binary search + combine + bias --------------------
__global__ void __launch_bounds__(256) out_kernel(const float* __restrict__ bo,
                                                  float* __restrict__ out) {
    const int i = blockIdx.x;
    const int b = i >> 11;
    const float tq = g_tQ[i];
    const float* ks = g_tKs + b * NSEQ;
    int lo = 0, hi = NSEQ;
    while (lo < hi) {                 // upper_bound: count of tK <= tQ
        int mid = (lo + hi) >> 1;
        if (ks[mid] <= tq) lo = mid + 1; else hi = mid;
    }
    const int r = lo;
    const float e2  = expf( 2.0f * tq);
    const float em2 = expf(-2.0f * tq);
    const int d = threadIdx.x * 4;
    const float4 p1  = *(const float4*)(g_P1 + ((size_t)b * (NSEQ + 1) + r)    * DDIM + d);
    const float4 p2  = *(const float4*)(g_P2 + ((size_t)b * (NSEQ + 1) + r)    * DDIM + d);
    const float4 p2t = *(const float4*)(g_P2 + ((size_t)b * (NSEQ + 1) + NSEQ) * DDIM + d);
    const float4 vs  = *(const float4*)(g_vsum + (size_t)b * DDIM + d);
    const float4 bb  = *(const float4*)(bo + d);
    const float A_STDP = 0.9f, W_OFF = 0.9f;
    float4 o;
    o.x = A_STDP * (e2 * (p2t.x - p2.x) - em2 * p1.x) + W_OFF * vs.x + bb.x;
    o.y = A_STDP * (e2 * (p2t.y - p2.y) - em2 * p1.y) + W_OFF * vs.y + bb.y;
    o.z = A_STDP * (e2 * (p2t.z - p2.z) - em2 * p1.z) + W_OFF * vs.z + bb.z;
    o.w = A_STDP * (e2 * (p2t.w - p2.w) - em2 * p1.w) + W_OFF * vs.w + bb.w;
    *(float4*)(out + (size_t)i * DDIM + d) = o;
}

// -----------------------------------------------------------------------------
extern "C" void kernel_launch(void* const* d_in, const int* in_sizes, int n_in,
                              void* d_out, int out_size) {
    const float* x  = (const float*)d_in[0];
    const float* Wq = (const float*)d_in[1];
    const float* gq = (const float*)d_in[2];
    const float* bq = (const float*)d_in[3];
    const float* mq = (const float*)d_in[4];
    const float* vq = (const float*)d_in[5];
    const float* Wk = (const float*)d_in[6];
    const float* gk = (const float*)d_in[7];
    const float* bk = (const float*)d_in[8];
    const float* mk = (const float*)d_in[9];
    const float* vk = (const float*)d_in[10];
    const float* Wv = (const float*)d_in[11];
    const float* gv = (const float*)d_in[12];
    const float* bv = (const float*)d_in[13];
    const float* mv = (const float*)d_in[14];
    const float* vv = (const float*)d_in[15];
    const float* Wo = (const float*)d_in[16];
    const float* bo = (const float*)d_in[17];
    float* out = (float*)d_out;

    cudaFuncSetAttribute(tc_gemm<0>, cudaFuncAttributeMaxDynamicSharedMemorySize, GEMM_SMEM);
    cudaFuncSetAttribute(tc_gemm<1>, cudaFuncAttributeMaxDynamicSharedMemorySize, GEMM_SMEM);
    cudaFuncSetAttribute(tc_gemm<2>, cudaFuncAttributeMaxDynamicSharedMemorySize, GEMM_SMEM);

    __nv_bfloat16 *xhi, *xlo, *wthi, *wtlo, *vhi, *vlo;
    float *qp, *kp;
    cudaGetSymbolAddress((void**)&xhi,  g_xhi);
    cudaGetSymbolAddress((void**)&xlo,  g_xlo);
    cudaGetSymbolAddress((void**)&wthi, g_WThi);
    cudaGetSymbolAddress((void**)&wtlo, g_WTlo);
    cudaGetSymbolAddress((void**)&vhi,  g_Vhi);
    cudaGetSymbolAddress((void**)&vlo,  g_Vlo);
    cudaGetSymbolAddress((void**)&qp,   g_qpart);
    cudaGetSymbolAddress((void**)&kp,   g_kpart);

    prep_x<<<MROWS * DDIM / 1024, 256>>>(x);
    prep_w<<<dim3(32, 32, 4), dim3(32, 8)>>>(Wq, Wk, Wv, Wo);

    const size_t WSZ = (size_t)DDIM * DDIM;
    dim3 gg(8, 128);   // (col tiles, row tiles)
    tc_gemm<0><<<gg, 256, GEMM_SMEM>>>(xhi, xlo, wthi + 0 * WSZ, wtlo + 0 * WSZ,
                                       mq, gq, vq, bq, qp);
    tc_gemm<0><<<gg, 256, GEMM_SMEM>>>(xhi, xlo, wthi + 1 * WSZ, wtlo + 1 * WSZ,
                                       mk, gk, vk, bk, kp);
    tc_gemm<1><<<gg, 256, GEMM_SMEM>>>(xhi, xlo, wthi + 2 * WSZ, wtlo + 2 * WSZ,
                                       mv, gv, vv, bv, nullptr);
    tc_gemm<2><<<gg, 256, GEMM_SMEM>>>(vhi, vlo, wthi + 3 * WSZ, wtlo + 3 * WSZ,
                                       nullptr, nullptr, nullptr, nullptr, nullptr);

    reduce_t_kernel<<<64, 256>>>();
    sort_kernel<<<NBATCH, 1024>>>();
    scanA_kernel<<<dim3(NSEG, NBATCH), 1024>>>();
    scanB_kernel<<<NBATCH, 1024>>>();
    scanC_kernel<<<dim3(NSEG, NBATCH), 1024>>>();
    out_kernel<<<MROWS, 256>>>(bo, out);
}